// round 1
// baseline (speedup 1.0000x reference)
#include <cuda_runtime.h>

// Problem constants
#define Bc 8
#define Nn 8192
#define Kk 6
#define Dd 256
#define Ll 5
#define BN 65536           // Bc*Nn
#define QLD 768            // qkv row stride

// ---------------- scratch (device globals; no allocation allowed) ----------------
__device__ float g_h  [(size_t)BN * Dd];
__device__ float g_hn [(size_t)BN * Dd];
__device__ float g_qkv[(size_t)BN * 3 * Dd];
__device__ float g_va [(size_t)BN * Dd];
__device__ float g_vb [(size_t)BN * Dd];
__device__ float g_ka [(size_t)BN * Dd];
__device__ float g_kb [(size_t)BN * Dd];
__device__ float g_scal[BN];
__device__ float g_kvm [Bc * Dd * Dd];
__device__ float g_ksum[Bc * Dd];

__device__ __forceinline__ float warp_sum(float v) {
#pragma unroll
    for (int o = 16; o > 0; o >>= 1) v += __shfl_xor_sync(0xffffffffu, v, o);
    return v;
}

// ---------------- embed: h = x @ emb_w + emb_b  (D_IN=3) ----------------
__global__ void embed_kernel(const float* __restrict__ x,
                             const float* __restrict__ w,
                             const float* __restrict__ b) {
    int row = blockIdx.x;
    int t = threadIdx.x;
    float x0 = x[row * 3 + 0], x1 = x[row * 3 + 1], x2 = x[row * 3 + 2];
    g_h[(size_t)row * Dd + t] = b[t] + x0 * w[t] + x1 * w[Dd + t] + x2 * w[2 * Dd + t];
}

// ---------------- layernorm: hn = LN(h) * g + b ----------------
__global__ void ln_kernel(const float* __restrict__ g, const float* __restrict__ b) {
    int row = blockIdx.x;
    int t = threadIdx.x;
    float x = g_h[(size_t)row * Dd + t];
    float s = warp_sum(x);
    float s2 = warp_sum(x * x);
    __shared__ float sh1[8], sh2[8];
    int w = t >> 5, l = t & 31;
    if (l == 0) { sh1[w] = s; sh2[w] = s2; }
    __syncthreads();
    if (t == 0) {
        float a = 0.f, c = 0.f;
#pragma unroll
        for (int i = 0; i < 8; i++) { a += sh1[i]; c += sh2[i]; }
        sh1[0] = a; sh2[0] = c;
    }
    __syncthreads();
    float m = sh1[0] * (1.0f / Dd);
    float var = sh2[0] * (1.0f / Dd) - m * m;
    var = fmaxf(var, 0.0f);
    float inv = rsqrtf(var + 1e-5f);
    g_hn[(size_t)row * Dd + t] = (x - m) * inv * g[t] + b[t];
}

// ---------------- generic fp32 GEMM: C = op(A@W) ----------------
// 128x128x8 tile, 8x8 microtile, 256 threads.
// relu_limit: columns n < relu_limit get relu(v)+1e-6 (no bias on those GEMMs)
// rowscale:   v *= rowscale[m]   (per output row)
// addc:       C += v (residual) else C = v
__global__ __launch_bounds__(256) void gemm_kernel(
    const float* __restrict__ A, int lda, long sA,
    const float* __restrict__ W, int ldw, long sW,
    const float* __restrict__ bias,
    const float* __restrict__ rowscale, long sRS,
    float* __restrict__ C, int ldc, long sC,
    int Kdim, int relu_limit, int addc)
{
    int m0 = blockIdx.x * 128, n0 = blockIdx.y * 128;
    int bz = blockIdx.z;
    A += (long)bz * sA;
    W += (long)bz * sW;
    C += (long)bz * sC;
    if (rowscale) rowscale += (long)bz * sRS;

    __shared__ float As[8][129];
    __shared__ float Bs[8][128];

    int tid = threadIdx.x;
    int tx = tid & 15, ty = tid >> 4;           // 16x16 thread grid
    int ar = tid >> 1, ak = (tid & 1) * 4;      // A load: 128 rows x 8 k
    int bk = tid >> 5, bn = (tid & 31) * 4;     // B load: 8 k x 128 n

    float acc[8][8];
#pragma unroll
    for (int i = 0; i < 8; i++)
#pragma unroll
        for (int j = 0; j < 8; j++) acc[i][j] = 0.f;

    for (int k0 = 0; k0 < Kdim; k0 += 8) {
        float4 a4 = *(const float4*)(A + (long)(m0 + ar) * lda + k0 + ak);
        float4 b4 = *(const float4*)(W + (long)(k0 + bk) * ldw + n0 + bn);
        As[ak + 0][ar] = a4.x;
        As[ak + 1][ar] = a4.y;
        As[ak + 2][ar] = a4.z;
        As[ak + 3][ar] = a4.w;
        *(float4*)&Bs[bk][bn] = b4;
        __syncthreads();
#pragma unroll
        for (int kk = 0; kk < 8; kk++) {
            float arr[8], brr[8];
#pragma unroll
            for (int i = 0; i < 8; i++) arr[i] = As[kk][ty * 8 + i];
#pragma unroll
            for (int j = 0; j < 8; j++) brr[j] = Bs[kk][tx * 8 + j];
#pragma unroll
            for (int i = 0; i < 8; i++)
#pragma unroll
                for (int j = 0; j < 8; j++) acc[i][j] += arr[i] * brr[j];
        }
        __syncthreads();
    }

#pragma unroll
    for (int i = 0; i < 8; i++) {
        int m = m0 + ty * 8 + i;
        float rs = rowscale ? rowscale[m] : 1.0f;
#pragma unroll
        for (int j = 0; j < 8; j++) {
            int n = n0 + tx * 8 + j;
            float v = acc[i][j];
            if (rowscale) v *= rs;
            if (n < relu_limit) v = fmaxf(v, 0.0f) + 1e-6f;
            if (bias) v += bias[n];
            long off = (long)m * ldc + n;
            if (addc) C[off] += v;
            else C[off] = v;
        }
    }
}

// ---------------- zero ----------------
__global__ void zero_kernel(float4* __restrict__ p, long n4) {
    long i = (long)blockIdx.x * 256 + threadIdx.x;
    if (i < n4) p[i] = make_float4(0.f, 0.f, 0.f, 0.f);
}

// ---------------- spmm scatter: dst[knn[n,k]] += scale * src[n]  ----------------
// one thread per (edge, d4) : total BN*Kk*64 threads
__global__ void scatter_kernel(const int* __restrict__ knn,
                               const float* __restrict__ src, int sld,
                               float scale, float* __restrict__ dst) {
    long idx = (long)blockIdx.x * 256 + threadIdx.x;  // grid sized exactly
    int d4 = (int)(idx & 63);
    long e = idx >> 6;                 // edge index in [0, BN*Kk)
    long srow = e / Kk;                // source node (b*N + n)
    int b = (int)(srow >> 13);         // srow / Nn
    int j = knn[e];
    const float4 v = *(const float4*)(src + srow * sld + (d4 << 2));
    float* p = dst + ((long)((b << 13) + j)) * Dd + (d4 << 2);
    atomicAdd(p + 0, v.x * scale);
    atomicAdd(p + 1, v.y * scale);
    atomicAdd(p + 2, v.z * scale);
    atomicAdd(p + 3, v.w * scale);
}

// ---------------- grf attn scalar: scal[row] = dot(q_row, k3_row) ----------------
__global__ void grfattn_kernel() {
    long gt = (long)blockIdx.x * 256 + threadIdx.x;
    int row = (int)(gt >> 5), lane = (int)(gt & 31);
    float s = 0.f;
#pragma unroll
    for (int it = 0; it < 8; it++) {
        int d = it * 32 + lane;
        s += g_qkv[(size_t)row * QLD + d] * g_ka[(size_t)row * Dd + d];
    }
    s = warp_sum(s);
    if (lane == 0) g_scal[row] = s;
}

// ---------------- ksum[b,d] = sum_n k[b,n,d] ----------------
__global__ void ksum_kernel() {
    int b = blockIdx.x >> 5, chunk = blockIdx.x & 31;
    int d = threadIdx.x;
    float s = 0.f;
    size_t base = ((size_t)b * Nn + (size_t)chunk * 256) * QLD + Dd + d;
    for (int r = 0; r < 256; r++) s += g_qkv[base + (size_t)r * QLD];
    atomicAdd(&g_ksum[b * Dd + d], s);
}

// ---------------- kv[b,d,e] = sum_n k[b,n,d]*v[b,n,e]  (split-K over n) ----------------
__global__ __launch_bounds__(256) void kveinsum_kernel() {
    int d0 = blockIdx.x * 64, e0 = blockIdx.y * 64;
    int b = blockIdx.z >> 3, chunk = blockIdx.z & 7;
    size_t base = ((size_t)b * Nn + (size_t)chunk * 1024) * QLD;
    __shared__ float Ks[16][64];
    __shared__ float Vs[16][64];
    int tid = threadIdx.x;
    int tx = tid & 15, ty = tid >> 4;
    int lk = tid >> 4, lq = (tid & 15) * 4;
    float acc[4][4];
#pragma unroll
    for (int i = 0; i < 4; i++)
#pragma unroll
        for (int j = 0; j < 4; j++) acc[i][j] = 0.f;

    for (int n0 = 0; n0 < 1024; n0 += 16) {
        float4 k4 = *(const float4*)(&g_qkv[base + (size_t)(n0 + lk) * QLD + Dd + d0 + lq]);
        float4 v4 = *(const float4*)(&g_qkv[base + (size_t)(n0 + lk) * QLD + 2 * Dd + e0 + lq]);
        *(float4*)&Ks[lk][lq] = k4;
        *(float4*)&Vs[lk][lq] = v4;
        __syncthreads();
#pragma unroll
        for (int kk = 0; kk < 16; kk++) {
            float a[4], c[4];
#pragma unroll
            for (int i = 0; i < 4; i++) a[i] = Ks[kk][ty * 4 + i];
#pragma unroll
            for (int j = 0; j < 4; j++) c[j] = Vs[kk][tx * 4 + j];
#pragma unroll
            for (int i = 0; i < 4; i++)
#pragma unroll
                for (int j = 0; j < 4; j++) acc[i][j] += a[i] * c[j];
        }
        __syncthreads();
    }
#pragma unroll
    for (int i = 0; i < 4; i++)
#pragma unroll
        for (int j = 0; j < 4; j++)
            atomicAdd(&g_kvm[(size_t)b * Dd * Dd + (size_t)(d0 + ty * 4 + i) * Dd + e0 + tx * 4 + j],
                      acc[i][j]);
}

// ---------------- z[row] = 1/(dot(q_row, ksum[b]) + 1e-6) ----------------
__global__ void zcalc_kernel() {
    long gt = (long)blockIdx.x * 256 + threadIdx.x;
    int row = (int)(gt >> 5), lane = (int)(gt & 31);
    int b = row >> 13;
    float s = 0.f;
#pragma unroll
    for (int it = 0; it < 8; it++) {
        int d = it * 32 + lane;
        s += g_qkv[(size_t)row * QLD + d] * g_ksum[b * Dd + d];
    }
    s = warp_sum(s);
    if (lane == 0) g_scal[row] = 1.0f / (s + 1e-6f);
}

// ---------------- head: out = h @ head_w + head_b  (3 cols) ----------------
__global__ void head_kernel(const float* __restrict__ w,
                            const float* __restrict__ hb,
                            float* __restrict__ out) {
    long gt = (long)blockIdx.x * 256 + threadIdx.x;
    int row = (int)(gt >> 5), lane = (int)(gt & 31);
    float a0 = 0.f, a1 = 0.f, a2 = 0.f;
#pragma unroll
    for (int it = 0; it < 8; it++) {
        int d = it * 32 + lane;
        float hv = g_h[(size_t)row * Dd + d];
        a0 += hv * w[d * 3 + 0];
        a1 += hv * w[d * 3 + 1];
        a2 += hv * w[d * 3 + 2];
    }
    a0 = warp_sum(a0);
    a1 = warp_sum(a1);
    a2 = warp_sum(a2);
    if (lane == 0) {
        out[(size_t)row * 3 + 0] = a0 + hb[0];
        out[(size_t)row * 3 + 1] = a1 + hb[1];
        out[(size_t)row * 3 + 2] = a2 + hb[2];
    }
}

// =============================== host ===============================
extern "C" void kernel_launch(void* const* d_in, const int* in_sizes, int n_in,
                              void* d_out, int out_size) {
    const float* x        = (const float*)d_in[0];
    const int*   knn      = (const int*)  d_in[1];
    const float* emb_w    = (const float*)d_in[2];
    const float* emb_b    = (const float*)d_in[3];
    const float* norm_g   = (const float*)d_in[4];
    const float* norm_b   = (const float*)d_in[5];
    const float* grf_qkv  = (const float*)d_in[6];
    const float* grf_outw = (const float*)d_in[7];
    const float* grf_outb = (const float*)d_in[8];
    const float* attn_qkv = (const float*)d_in[9];
    const float* attn_outw= (const float*)d_in[10];
    const float* attn_outb= (const float*)d_in[11];
    const float* head_w   = (const float*)d_in[12];
    const float* head_b   = (const float*)d_in[13];
    float* out = (float*)d_out;

    float *h, *hn, *qkv, *va, *vb, *ka, *kb, *scal, *kvm, *ksum;
    cudaGetSymbolAddress((void**)&h,    g_h);
    cudaGetSymbolAddress((void**)&hn,   g_hn);
    cudaGetSymbolAddress((void**)&qkv,  g_qkv);
    cudaGetSymbolAddress((void**)&va,   g_va);
    cudaGetSymbolAddress((void**)&vb,   g_vb);
    cudaGetSymbolAddress((void**)&ka,   g_ka);
    cudaGetSymbolAddress((void**)&kb,   g_kb);
    cudaGetSymbolAddress((void**)&scal, g_scal);
    cudaGetSymbolAddress((void**)&kvm,  g_kvm);
    cudaGetSymbolAddress((void**)&ksum, g_ksum);

    const float s_hop = 1.0f / ((float)Kk + 1e-6f);
    const long bnD4 = (long)BN * Dd / 4;   // float4 count of a [BN,D] buffer
    const int zgrid = (int)((bnD4 + 255) / 256);
    const int sgrid = (int)(((long)BN * Kk * 64) / 256);   // exact

    // embed
    embed_kernel<<<BN, Dd>>>(x, emb_w, emb_b);

    for (int i = 0; i < Ll; i++) {
        // ===== GRF block =====
        ln_kernel<<<BN, Dd>>>(norm_g + (size_t)(2 * i) * Dd, norm_b + (size_t)(2 * i) * Dd);
        // qkv = hn @ grf_qkv[i]
        gemm_kernel<<<dim3(BN / 128, 6, 1), 256>>>(
            hn, Dd, 0, grf_qkv + (size_t)i * Dd * 3 * Dd, QLD, 0,
            nullptr, nullptr, 0, qkv, QLD, 0, Dd, 0, 0);
        // v hops (3)
        zero_kernel<<<zgrid, 256>>>((float4*)va, bnD4);
        scatter_kernel<<<sgrid, 256>>>(knn, qkv + 2 * Dd, QLD, s_hop, va);
        zero_kernel<<<zgrid, 256>>>((float4*)vb, bnD4);
        scatter_kernel<<<sgrid, 256>>>(knn, va, Dd, s_hop, vb);
        zero_kernel<<<zgrid, 256>>>((float4*)va, bnD4);
        scatter_kernel<<<sgrid, 256>>>(knn, vb, Dd, s_hop, va);
        // k hops (3)
        zero_kernel<<<zgrid, 256>>>((float4*)ka, bnD4);
        scatter_kernel<<<sgrid, 256>>>(knn, qkv + Dd, QLD, s_hop, ka);
        zero_kernel<<<zgrid, 256>>>((float4*)kb, bnD4);
        scatter_kernel<<<sgrid, 256>>>(knn, ka, Dd, s_hop, kb);
        zero_kernel<<<zgrid, 256>>>((float4*)ka, bnD4);
        scatter_kernel<<<sgrid, 256>>>(knn, kb, Dd, s_hop, ka);
        // attn scalar = dot(q, k3)
        grfattn_kernel<<<BN * 32 / 256, 256>>>();
        // h += (attn * v3) @ grf_outw[i] + grf_outb[i]
        gemm_kernel<<<dim3(BN / 128, 2, 1), 256>>>(
            va, Dd, 0, grf_outw + (size_t)i * Dd * Dd, Dd, 0,
            grf_outb + (size_t)i * Dd, scal, 0, h, Dd, 0, Dd, 0, 1);

        // ===== linear attention block =====
        ln_kernel<<<BN, Dd>>>(norm_g + (size_t)(2 * i + 1) * Dd, norm_b + (size_t)(2 * i + 1) * Dd);
        // qkv = hn @ attn_qkv[i], relu+1e-6 on q,k columns (<512)
        gemm_kernel<<<dim3(BN / 128, 6, 1), 256>>>(
            hn, Dd, 0, attn_qkv + (size_t)i * Dd * 3 * Dd, QLD, 0,
            nullptr, nullptr, 0, qkv, QLD, 0, Dd, 2 * Dd, 0);
        // ksum
        zero_kernel<<<2, 256>>>((float4*)ksum, (long)Bc * Dd / 4);
        ksum_kernel<<<Bc * 32, 256>>>();
        // kv = k^T v  (per batch, split-K over n with atomics)
        zero_kernel<<<(Bc * Dd * Dd / 4 + 255) / 256, 256>>>((float4*)kvm, (long)Bc * Dd * Dd / 4);
        kveinsum_kernel<<<dim3(4, 4, Bc * 8), 256>>>();
        // z scalar
        zcalc_kernel<<<BN * 32 / 256, 256>>>();
        // vb = z * (q @ kv)   (batched)
        gemm_kernel<<<dim3(Nn / 128, 2, Bc), 256>>>(
            qkv, QLD, (long)Nn * QLD, kvm, Dd, (long)Dd * Dd,
            nullptr, scal, Nn, vb, Dd, (long)Nn * Dd, Dd, 0, 0);
        // h += vb @ attn_outw[i] + attn_outb[i]
        gemm_kernel<<<dim3(BN / 128, 2, 1), 256>>>(
            vb, Dd, 0, attn_outw + (size_t)i * Dd * Dd, Dd, 0,
            attn_outb + (size_t)i * Dd, nullptr, 0, h, Dd, 0, Dd, 0, 1);
    }

    // head
    head_kernel<<<BN * 32 / 256, 256>>>(head_w, head_b, out);
}